// round 12
// baseline (speedup 1.0000x reference)
#include <cuda_runtime.h>
#include <math_constants.h>

// Cumulative max along H for x[B=32, C=1, H=1024, W=2048] fp32.
// Single streaming pass: 256 MB read + 256 MB write (the traffic floor).
//
// R9 = R5 config (the measured optimum: float2 columns, 32768 threads,
// 1024x32 grid -> 6.9 warps/SM, rolling ring-buffer pipeline, streaming
// cache hints) with pipeline depth raised U=32 -> 44 (under the ~55
// per-warp outstanding-LDG cap). Longer independent load runs between
// SB-bound consume windows smooth the DRAM read stream; traffic
// unchanged. R6 (scalar, 2x warps), R7 (float4, 0.5x warps) and R8
// (paired issue) all measured worse or neutral -> this axis is the
// last untested knob before declaring the HBM mixed-stream ceiling.

static constexpr int B = 32;
static constexpr int H = 1024;
static constexpr int W = 2048;
static constexpr int W2 = W / 2;             // 1024 float2 per row
static constexpr int NCOLS = B * W2;         // 32768 threads
static constexpr int U = 44;                 // pipeline depth (float2 loads)
static constexpr int NFULL = (H / U) - 1;    // 22 full steady-state chunks
static constexpr int TAIL = H - NFULL * U;   // 56 rows: 44 buffered + 12 direct

__global__ void __launch_bounds__(32)
cummax_h_kernel(const float2* __restrict__ x, float2* __restrict__ out) {
    int c = blockIdx.x * blockDim.x + threadIdx.x;   // 0 .. NCOLS-1

    int b  = c >> 10;          // c / 1024
    int w2 = c & (W2 - 1);     // c % 1024

    const float2* __restrict__ p = x   + (size_t)b * H * W2 + w2;
    float2*       __restrict__ q = out + (size_t)b * H * W2 + w2;

    float2 m = make_float2(-CUDART_INF_F, -CUDART_INF_F);

    float2 buf[U];

    // Prologue: fill the pipeline with rows 0..U-1.
    #pragma unroll
    for (int i = 0; i < U; i++)
        buf[i] = __ldcs(p + (size_t)i * W2);

    // Steady state: consume row hCur+i while refilling with row hCur+i+U.
    // Refill load is independent of the fmax chain and issues first, so
    // U LDG.64 stay outstanding per thread continuously (no drain).
    for (int cc = 0; cc < NFULL; cc++) {
        int hCur = cc * U;
        int hNxt = hCur + U;
        #pragma unroll
        for (int i = 0; i < U; i++) {
            float2 v = buf[i];
            buf[i] = __ldcs(p + (size_t)(hNxt + i) * W2);
            m.x = fmaxf(m.x, v.x);
            m.y = fmaxf(m.y, v.y);
            __stcs(q + (size_t)(hCur + i) * W2, m);
        }
    }

    // Epilogue: drain the buffer, then finish the last TAIL-U rows directly.
    {
        int hCur = NFULL * U;
        #pragma unroll
        for (int i = 0; i < U; i++) {
            m.x = fmaxf(m.x, buf[i].x);
            m.y = fmaxf(m.y, buf[i].y);
            __stcs(q + (size_t)(hCur + i) * W2, m);
        }
        #pragma unroll
        for (int i = U; i < TAIL; i++) {
            float2 v = __ldcs(p + (size_t)(hCur + i) * W2);
            m.x = fmaxf(m.x, v.x);
            m.y = fmaxf(m.y, v.y);
            __stcs(q + (size_t)(hCur + i) * W2, m);
        }
    }
}

extern "C" void kernel_launch(void* const* d_in, const int* in_sizes, int n_in,
                              void* d_out, int out_size) {
    const float2* x   = (const float2*)d_in[0];
    float2*       out = (float2*)d_out;

    // 1024 blocks x 32 threads = 32768 threads, one per float2 column.
    cummax_h_kernel<<<NCOLS / 32, 32>>>(x, out);
}

// round 14
// speedup vs baseline: 1.0829x; 1.0829x over previous
#include <cuda_runtime.h>
#include <math_constants.h>

// Cumulative max along H for x[B=32, C=1, H=1024, W=2048] fp32.
// Single streaming pass: 256 MB read + 256 MB write (the traffic floor).
//
// FINAL (= R5, the measured optimum across the full design sweep):
//   width axis:  float4 66.9% < float2 78.6% > float1 76.5% DRAM
//   depth axis:  chunked-16 68.4% < rolling-32 78.6% > rolling-44 73.7%
//                (U=44 blew regs 100->158 and broke the LDG/FMNMX/STG
//                 interleave)
//   issue pairing: neutral. Traffic: single pass is the floor.
//
// float2 column per thread (32768 threads, 1024 blocks x 32 -> 6.9
// warps/SM), rolling ring-buffer pipeline depth U=32: each step refills
// buf[i] with the row U ahead BEFORE consuming, so 256 B/thread (~8 MB
// chip-wide) stays continuously in flight with no drain windows.
// ~6.24 TB/s on a 50/50 interleaved R/W stream == the practical HBM3e
// ceiling; L2 (38%), LSU and issue (5.5%) all have headroom.

static constexpr int B = 32;
static constexpr int H = 1024;
static constexpr int W = 2048;
static constexpr int W2 = W / 2;            // 1024 float2 per row
static constexpr int NCOLS = B * W2;        // 32768 threads
static constexpr int U = 32;                // pipeline depth (float2 loads)
static constexpr int NCHUNK = H / U;        // 32 chunks

__global__ void __launch_bounds__(32)
cummax_h_kernel(const float2* __restrict__ x, float2* __restrict__ out) {
    int c = blockIdx.x * blockDim.x + threadIdx.x;   // 0 .. NCOLS-1

    int b  = c >> 10;          // c / 1024
    int w2 = c & (W2 - 1);     // c % 1024

    const float2* __restrict__ p = x   + (size_t)b * H * W2 + w2;
    float2*       __restrict__ q = out + (size_t)b * H * W2 + w2;

    float2 m = make_float2(-CUDART_INF_F, -CUDART_INF_F);

    float2 buf[U];

    // Prologue: fill the pipeline with rows 0..U-1.
    #pragma unroll
    for (int i = 0; i < U; i++)
        buf[i] = __ldcs(p + (size_t)i * W2);

    // Steady state: consume row hCur+i while refilling with row hCur+i+U.
    // The refill load is independent of the fmax chain and issues first,
    // so U loads stay in flight continuously with no drain windows.
    for (int cc = 0; cc < NCHUNK - 1; cc++) {
        int hCur = cc * U;
        int hNxt = hCur + U;
        #pragma unroll
        for (int i = 0; i < U; i++) {
            float2 v = buf[i];
            buf[i] = __ldcs(p + (size_t)(hNxt + i) * W2);
            m.x = fmaxf(m.x, v.x);
            m.y = fmaxf(m.y, v.y);
            __stcs(q + (size_t)(hCur + i) * W2, m);
        }
    }

    // Epilogue: drain the last chunk (rows H-U .. H-1).
    {
        int hCur = (NCHUNK - 1) * U;
        #pragma unroll
        for (int i = 0; i < U; i++) {
            m.x = fmaxf(m.x, buf[i].x);
            m.y = fmaxf(m.y, buf[i].y);
            __stcs(q + (size_t)(hCur + i) * W2, m);
        }
    }
}

extern "C" void kernel_launch(void* const* d_in, const int* in_sizes, int n_in,
                              void* d_out, int out_size) {
    const float2* x   = (const float2*)d_in[0];
    float2*       out = (float2*)d_out;

    // 1024 blocks x 32 threads = 32768 threads, one per float2 column.
    cummax_h_kernel<<<NCOLS / 32, 32>>>(x, out);
}